// round 9
// baseline (speedup 1.0000x reference)
#include <cuda_runtime.h>
#include <cuda_bf16.h>
#include <math.h>
#include <stdint.h>

#define BDIM   32
#define TIN    1000
#define TA     400
#define FDIM   256
#define HDIM   256
#define FRAME  320
#define SHIFT  160
#define LSIG   160000
#define LAUX   64000
#define NCLS   101
#define NSLC   8
#define SLC    (TA / NSLC)

// ---------------- scratch ----------------
__device__ float g_out   [BDIM * TIN * FDIM];
__device__ float g_out2  [BDIM * TIN * FDIM];
__device__ float g_aux   [BDIM * TA  * FDIM];
__device__ float g_h     [BDIM * TA  * HDIM];
__device__ float g_a     [BDIM * TA  * HDIM];
__device__ float g_logits[BDIM * TA  * HDIM];
__device__ float g_y     [BDIM * TIN * FRAME];
__device__ float g_bias2 [BDIM * HDIM];
__device__ float g_emb   [BDIM * FDIM];
__device__ float g_evec  [4 * BDIM * FDIM];
__device__ float g_glnp  [BDIM * 16 * 2];
__device__ float g_hpart [BDIM * NSLC * HDIM * 2];
__device__ float g_ppart [BDIM * NSLC * HDIM * 4];

// bf16 split weight planes, layout [N][K]
__device__ __nv_bfloat16 w_in_hi [256 * 320];
__device__ __nv_bfloat16 w_in_lo [256 * 320];
__device__ __nv_bfloat16 w_ec_hi [256 * 256];
__device__ __nv_bfloat16 w_ec_lo [256 * 256];
__device__ __nv_bfloat16 w_a1_hi [256 * 256];
__device__ __nv_bfloat16 w_a1_lo [256 * 256];
__device__ __nv_bfloat16 w_a2_hi [256 * 256];
__device__ __nv_bfloat16 w_a2_lo [256 * 256];
__device__ __nv_bfloat16 w_arn_hi[4 * 256 * 256];
__device__ __nv_bfloat16 w_arn_lo[4 * 256 * 256];
__device__ __nv_bfloat16 w_out_hi[320 * 256];
__device__ __nv_bfloat16 w_out_lo[320 * 256];

// ---------------- helpers ----------------
__device__ __forceinline__ uint32_t smem_u32(const void* p) {
    uint32_t a;
    asm("{ .reg .u64 t; cvta.to.shared.u64 t, %1; cvt.u32.u64 %0, t; }" : "=r"(a) : "l"(p));
    return a;
}
__device__ __forceinline__ void ldmx4(uint32_t* r, uint32_t addr) {
    asm volatile("ldmatrix.sync.aligned.m8n8.x4.shared.b16 {%0,%1,%2,%3}, [%4];"
                 : "=r"(r[0]), "=r"(r[1]), "=r"(r[2]), "=r"(r[3]) : "r"(addr));
}
__device__ __forceinline__ void ldmx2(uint32_t* r, uint32_t addr) {
    asm volatile("ldmatrix.sync.aligned.m8n8.x2.shared.b16 {%0,%1}, [%2];"
                 : "=r"(r[0]), "=r"(r[1]) : "r"(addr));
}
__device__ __forceinline__ void mma_bf16(float* c, const uint32_t* a, const uint32_t* b) {
    asm volatile("mma.sync.aligned.m16n8k16.row.col.f32.bf16.bf16.f32 "
                 "{%0,%1,%2,%3}, {%4,%5,%6,%7}, {%8,%9}, {%0,%1,%2,%3};"
                 : "+f"(c[0]), "+f"(c[1]), "+f"(c[2]), "+f"(c[3])
                 : "r"(a[0]), "r"(a[1]), "r"(a[2]), "r"(a[3]), "r"(b[0]), "r"(b[1]));
}
__device__ __forceinline__ void cp16(uint32_t saddr, const void* gaddr) {
    asm volatile("cp.async.ca.shared.global [%0], [%1], 16;" :: "r"(saddr), "l"(gaddr));
}
__device__ __forceinline__ void cp_commit() { asm volatile("cp.async.commit_group;" ::: "memory"); }
template<int W> __device__ __forceinline__ void cp_wait() {
    asm volatile("cp.async.wait_group %0;" :: "n"(W) : "memory");
}
// 128B rows, XOR swizzle on 16B chunks
__device__ __forceinline__ uint32_t SWZ(int row, int chunk) {
    return ((uint32_t)row << 7) + ((uint32_t)((chunk ^ (row & 7)) & 7) << 4);
}

// ---------------- weight prep: tiled transpose + split ----------------
struct PrepArgs {
    const float* src[10];
    __nv_bfloat16* hi[10];
    __nv_bfloat16* lo[10];
    int K[10];
    int N[10];
    int toff[11];
};
__global__ __launch_bounds__(256) void k_prep_all(PrepArgs a)
{
    __shared__ float tile[32][33];
    int tb = blockIdx.x;
    int r = 0;
    while (tb >= a.toff[r + 1]) r++;
    int ti = tb - a.toff[r];
    const int K = a.K[r], N = a.N[r];
    const int ntn = N / 32;
    const int tk = ti / ntn, tn = ti - tk * ntn;
    const int ty = threadIdx.x >> 5, tx = threadIdx.x & 31;
    #pragma unroll
    for (int q = 0; q < 4; q++) {
        const int k = tk * 32 + ty + q * 8;
        tile[ty + q * 8][tx] = a.src[r][(size_t)k * N + tn * 32 + tx];
    }
    __syncthreads();
    #pragma unroll
    for (int q = 0; q < 4; q++) {
        const int n = tn * 32 + ty + q * 8;
        float x = tile[tx][ty + q * 8];
        __nv_bfloat16 h = __float2bfloat16(x);
        const size_t o = (size_t)n * K + tk * 32 + tx;
        a.hi[r][o] = h;
        a.lo[r][o] = __float2bfloat16(x - __bfloat162float(h));
    }
}

// ---------------- tensor-core GEMM: 256 threads, MT=64, swizzled smem, OCC CTAs/SM ----------------
template<int NT, int MODE, int OCC>
__global__ void __launch_bounds__(256, OCC) k_tgemm(
    const float* __restrict__ Ain,
    const __nv_bfloat16* __restrict__ Bhi, const __nv_bfloat16* __restrict__ Blo,
    float* __restrict__ Cin,
    const float* __restrict__ e0, const float* __restrict__ e1, const float* __restrict__ e2,
    const int* __restrict__ aux_len, int Min, int K, int Nfull, int Lin, int arn_i,
    const float* A2, float* C2, int M2, int L2, int split)
{
    constexpr int MT   = 64;
    constexpr int WN   = NT / 4;     // 32 or 40
    constexpr int NF   = WN / 8;     // 4 or 5
    constexpr int MI   = 2;
    constexpr int APL  = MT * 128;   // 8192 B per A plane
    constexpr int BPL  = NT * 128;

    extern __shared__ char smem[];
    const uint32_t sb = smem_u32(smem);
    const uint32_t aH = sb;
    const uint32_t aL = sb + APL;
    const uint32_t bH = sb + 2 * APL;
    const uint32_t bL = sb + 2 * APL + BPL;

    const int tid  = threadIdx.x;
    const int w    = tid >> 5;
    const int lane = tid & 31;
    const int b    = blockIdx.y;
    const int nbase = blockIdx.z * NT;

    const float* A = Ain;
    float* C = Cin;
    int M = Min, L = Lin;
    int bx = blockIdx.x;
    if (MODE == 0 && split > 0 && bx >= split) {
        A = A2; C = C2; M = M2; L = L2; bx -= split;
    }
    const int t0 = bx * MT;
    const int NB = K / 64;
    const int wm = w >> 2;
    const int wn = w & 3;
    const int wn0 = wn * WN;

    int   len  = 0;
    float mean = 0.f, inv = 0.f;
    if (MODE == 1) {
        len = aux_len[b];
        double s = 0.0, q = 0.0;
        #pragma unroll
        for (int i = 0; i < 16; i++) {
            s += (double)g_glnp[(b * 16 + i) * 2 + 0];
            q += (double)g_glnp[(b * 16 + i) * 2 + 1];
        }
        const double n = (double)len * FDIM;
        double m = s / n;
        double var = q / n - m * m;
        mean = (float)m;
        inv  = (float)(1.0 / sqrt(var + 1e-5));
    }

    const int arow = tid >> 2;
    const int achk = (tid & 3) * 2;
    const int ac0  = achk * 8;

    float acc[MI][NF][4];
    #pragma unroll
    for (int mi = 0; mi < MI; mi++)
        #pragma unroll
        for (int nj = 0; nj < NF; nj++)
            #pragma unroll
            for (int q = 0; q < 4; q++) acc[mi][nj][q] = 0.f;

    auto stageA = [&](int kb) {
        const int t = t0 + arow;
        float va[16];
        if (MODE == 0) {
            if (t < M) {
                const float* src = A + (size_t)b * L;
                const int base = t * SHIFT + kb * 64 + ac0;
                #pragma unroll
                for (int q = 0; q < 4; q++) {
                    const int p = base + q * 4;
                    if (p + 3 < L) {
                        float4 f = *(const float4*)(src + p);
                        va[q*4+0]=f.x; va[q*4+1]=f.y; va[q*4+2]=f.z; va[q*4+3]=f.w;
                    } else {
                        #pragma unroll
                        for (int j = 0; j < 4; j++) va[q*4+j] = (p + j < L) ? src[p + j] : 0.f;
                    }
                }
            } else {
                #pragma unroll
                for (int j = 0; j < 16; j++) va[j] = 0.f;
            }
        } else {
            const bool valid = (MODE == 1) ? (t < len) : (t < M);
            if (valid) {
                const float* src = A + ((size_t)b * M + t) * K + kb * 64 + ac0;
                #pragma unroll
                for (int q = 0; q < 4; q++) {
                    float4 f = *(const float4*)(src + q * 4);
                    va[q*4+0]=f.x; va[q*4+1]=f.y; va[q*4+2]=f.z; va[q*4+3]=f.w;
                }
                if (MODE == 1) {
                    const int c0 = kb * 64 + ac0;
                    #pragma unroll
                    for (int q = 0; q < 4; q++) {
                        float4 gg = *(const float4*)(e0 + c0 + q * 4);
                        float4 gb = *(const float4*)(e1 + c0 + q * 4);
                        va[q*4+0] = gg.x * inv * (va[q*4+0] - mean) + gb.x;
                        va[q*4+1] = gg.y * inv * (va[q*4+1] - mean) + gb.y;
                        va[q*4+2] = gg.z * inv * (va[q*4+2] - mean) + gb.z;
                        va[q*4+3] = gg.w * inv * (va[q*4+3] - mean) + gb.w;
                    }
                }
            } else {
                #pragma unroll
                for (int j = 0; j < 16; j++) va[j] = 0.f;
            }
        }
        #pragma unroll
        for (int q = 0; q < 2; q++) {
            union { __nv_bfloat16 x[8]; uint4 v; } H, Lo;
            #pragma unroll
            for (int j = 0; j < 8; j++) {
                float f = va[q * 8 + j];
                __nv_bfloat16 hb = __float2bfloat16(f);
                H.x[j]  = hb;
                Lo.x[j] = __float2bfloat16(f - __bfloat162float(hb));
            }
            const uint32_t so = SWZ(arow, achk + q);
            *(uint4*)(smem + so)       = H.v;
            *(uint4*)(smem + APL + so) = Lo.v;
        }
    };
    auto cpB = [&](int kb) {
        for (int idx = tid; idx < NT * 8; idx += 256) {
            const int n = idx >> 3, c = idx & 7;
            const uint32_t so = SWZ(n, c);
            cp16(bH + so, Bhi + (size_t)(nbase + n) * K + kb * 64 + c * 8);
            cp16(bL + so, Blo + (size_t)(nbase + n) * K + kb * 64 + c * 8);
        }
    };
    // B fragments processed in pairs to cap live registers (~8 B-frag regs live)
    auto compute = [&]() {
        #pragma unroll
        for (int ki = 0; ki < 4; ki++) {
            #pragma unroll
            for (int p = 0; p < NF / 2; p++) {
                uint32_t bhp[4], blp[4];
                {
                    const int g = lane >> 3;
                    const int nrow = wn0 + p * 16 + ((g >> 1) << 3) + (lane & 7);
                    const int chunk = ki * 2 + (g & 1);
                    const uint32_t off = SWZ(nrow, chunk);
                    ldmx4(bhp, bH + off);
                    ldmx4(blp, bL + off);
                }
                #pragma unroll
                for (int mi = 0; mi < MI; mi++) {
                    uint32_t ah[4], al[4];
                    const int row = wm * 32 + mi * 16 + (lane & 15);
                    const int chunk = ki * 2 + (lane >> 4);
                    const uint32_t off = SWZ(row, chunk);
                    ldmx4(ah, aH + off);
                    ldmx4(al, aL + off);
                    #pragma unroll
                    for (int j = 0; j < 2; j++) {
                        mma_bf16(acc[mi][2*p+j], ah, bhp + 2*j);
                        mma_bf16(acc[mi][2*p+j], ah, blp + 2*j);
                        mma_bf16(acc[mi][2*p+j], al, bhp + 2*j);
                    }
                }
            }
            if (NF & 1) {
                const int nj = NF - 1;
                uint32_t bhp[2], blp[2];
                {
                    const int nrow = wn0 + nj * 8 + (lane & 7);
                    const int chunk = ki * 2 + ((lane & 15) >> 3);
                    const uint32_t off = SWZ(nrow, chunk);
                    ldmx2(bhp, bH + off);
                    ldmx2(blp, bL + off);
                }
                #pragma unroll
                for (int mi = 0; mi < MI; mi++) {
                    uint32_t ah[4], al[4];
                    const int row = wm * 32 + mi * 16 + (lane & 15);
                    const int chunk = ki * 2 + (lane >> 4);
                    const uint32_t off = SWZ(row, chunk);
                    ldmx4(ah, aH + off);
                    ldmx4(al, aL + off);
                    mma_bf16(acc[mi][nj], ah, bhp);
                    mma_bf16(acc[mi][nj], ah, blp);
                    mma_bf16(acc[mi][nj], al, bhp);
                }
            }
        }
    };

    for (int kb = 0; kb < NB; kb++) {
        cpB(kb);
        cp_commit();
        stageA(kb);
        cp_wait<0>();
        __syncthreads();
        compute();
        __syncthreads();
    }

    #pragma unroll
    for (int mi = 0; mi < MI; mi++) {
        #pragma unroll
        for (int half = 0; half < 2; half++) {
            const int r = wm * 32 + mi * 16 + (lane >> 2) + half * 8;
            const int t = t0 + r;
            if (t >= M) continue;
            #pragma unroll
            for (int nj = 0; nj < NF; nj++) {
                const int col = nbase + wn0 + nj * 8 + (lane & 3) * 2;
                float v0 = acc[mi][nj][half * 2 + 0];
                float v1 = acc[mi][nj][half * 2 + 1];
                float r0, r1;
                if (MODE == 0) {
                    r0 = v0 + e0[col]; r1 = v1 + e0[col + 1];
                } else if (MODE == 1) {
                    if (t < len) { r0 = fmaxf(v0 + e2[col], 0.f); r1 = fmaxf(v1 + e2[col + 1], 0.f); }
                    else         { r0 = 0.f; r1 = 0.f; }
                } else if (MODE == 2) {
                    float a0 = fmaxf(v0 + g_bias2[b * HDIM + col],     0.f);
                    float a1 = fmaxf(v1 + g_bias2[b * HDIM + col + 1], 0.f);
                    r0 = tanhf(a0 * e0[col]     + e1[col]);
                    r1 = tanhf(a1 * e0[col + 1] + e1[col + 1]);
                } else if (MODE == 3) {
                    r0 = v0 + e0[col]; r1 = v1 + e0[col + 1];
                } else {
                    const float* ares = A + ((size_t)b * M + t) * K + col;
                    const float* ev   = g_evec + ((size_t)arn_i * BDIM + b) * FDIM + col;
                    r0 = ares[0] + tanhf(v0 + ev[0] + e0[col]);
                    r1 = ares[1] + tanhf(v1 + ev[1] + e0[col + 1]);
                }
                *(float2*)(C + ((size_t)b * M + t) * Nfull + col) = make_float2(r0, r1);
            }
        }
    }
}

// ---------------- GLN partials ----------------
__global__ __launch_bounds__(256) void k_gln_part(const int* __restrict__ aux_len)
{
    const int b = blockIdx.x, s = blockIdx.y;
    const int len = aux_len[b];
    const int tA = s * (TA / 16);
    const int tB = min(len, tA + TA / 16);
    float sum = 0.f, sq = 0.f;
    if (tB > tA) {
        const float* p = g_aux + ((size_t)b * TA + tA) * FDIM;
        const int n = (tB - tA) * FDIM;
        for (int i = threadIdx.x; i < n; i += 256) {
            float v = p[i];
            sum += v; sq += v * v;
        }
    }
    __shared__ float ss[256], qq[256];
    ss[threadIdx.x] = sum; qq[threadIdx.x] = sq;
    __syncthreads();
    for (int st = 128; st > 0; st >>= 1) {
        if (threadIdx.x < st) { ss[threadIdx.x] += ss[threadIdx.x + st]; qq[threadIdx.x] += qq[threadIdx.x + st]; }
        __syncthreads();
    }
    if (threadIdx.x == 0) {
        g_glnp[(b * 16 + s) * 2 + 0] = ss[0];
        g_glnp[(b * 16 + s) * 2 + 1] = qq[0];
    }
}

// ---------------- h stats partials + combine ----------------
__global__ __launch_bounds__(256) void k_hpart(const int* __restrict__ aux_len)
{
    const int b = blockIdx.x, s = blockIdx.y, ch = threadIdx.x;
    const int len = aux_len[b];
    const int tA = s * SLC;
    const int tB = min(len, tA + SLC);
    float sum = 0.f, sq = 0.f;
    const float* p = g_h + ((size_t)b * TA) * HDIM + ch;
    for (int t = tA; t < tB; t++) {
        float v = p[(size_t)t * HDIM];
        sum += v; sq += v * v;
    }
    float* o = g_hpart + (((size_t)b * NSLC + s) * HDIM + ch) * 2;
    o[0] = sum; o[1] = sq;
}
__global__ __launch_bounds__(256) void k_hcomb(const int* __restrict__ aux_len,
                                               const float* __restrict__ att_w1,
                                               const float* __restrict__ att_b1)
{
    const int b = blockIdx.x, ch = threadIdx.x;
    const int len = aux_len[b];
    __shared__ float sm[256], sstd[256];
    {
        float sum = 0.f, sq = 0.f;
        #pragma unroll
        for (int s = 0; s < NSLC; s++) {
            const float* o = g_hpart + (((size_t)b * NSLC + s) * HDIM + ch) * 2;
            sum += o[0]; sq += o[1];
        }
        const float n = (float)len;
        const float m = sum / n;
        const float var = (sq - n * m * m) / (n - 1.f);
        sm[ch] = m;
        sstd[ch] = sqrtf(fmaxf(var, 1e-4f));
    }
    __syncthreads();
    float acc = att_b1[ch];
    for (int k = 0; k < HDIM; k++) {
        acc += sm[k]   * att_w1[(size_t)(256 + k) * HDIM + ch]
             + sstd[k] * att_w1[(size_t)(512 + k) * HDIM + ch];
    }
    g_bias2[b * HDIM + ch] = acc;
}

// ---------------- pool partials + combine ----------------
__global__ __launch_bounds__(256) void k_ppart(const int* __restrict__ aux_len)
{
    const int b = blockIdx.x, s = blockIdx.y, ch = threadIdx.x;
    const int len = aux_len[b];
    const int tA = s * SLC;
    const int tB = min(len, tA + SLC);
    const float* lp = g_logits + (size_t)b * TA * HDIM + ch;
    const float* hp = g_h      + (size_t)b * TA * HDIM + ch;
    float mx = -1e30f, se = 0.f, s1 = 0.f, s2 = 0.f;
    for (int t = tA; t < tB; t++) {
        float l  = lp[(size_t)t * HDIM];
        float hv = hp[(size_t)t * HDIM];
        if (l > mx) {
            float sc = expf(mx - l);
            se *= sc; s1 *= sc; s2 *= sc;
            mx = l;
        }
        float e = expf(l - mx);
        se += e; s1 += hv * e; s2 += hv * hv * e;
    }
    float* o = g_ppart + (((size_t)b * NSLC + s) * HDIM + ch) * 4;
    o[0] = mx; o[1] = se; o[2] = s1; o[3] = s2;
}
__global__ __launch_bounds__(256) void k_pcomb(const float* __restrict__ bn5g,
                                               const float* __restrict__ bn5b,
                                               const float* __restrict__ fc6_w,
                                               const float* __restrict__ fc6_b,
                                               const float* __restrict__ bn6g,
                                               const float* __restrict__ bn6b,
                                               const float* __restrict__ cls_w,
                                               const float* __restrict__ cls_b,
                                               const float* __restrict__ arn_w2,
                                               float* __restrict__ out_cls, int write_cls)
{
    const int b = blockIdx.x, j = threadIdx.x;
    __shared__ float e[2 * HDIM];
    {
        float mx = -1e30f;
        float pm[NSLC];
        #pragma unroll
        for (int s = 0; s < NSLC; s++) {
            pm[s] = g_ppart[(((size_t)b * NSLC + s) * HDIM + j) * 4];
            mx = fmaxf(mx, pm[s]);
        }
        float se = 0.f, s1 = 0.f, s2 = 0.f;
        #pragma unroll
        for (int s = 0; s < NSLC; s++) {
            const float* o = g_ppart + (((size_t)b * NSLC + s) * HDIM + j) * 4;
            float sc = expf(pm[s] - mx);
            se += o[1] * sc; s1 += o[2] * sc; s2 += o[3] * sc;
        }
        float mu = s1 / se;
        float sg = sqrtf(fmaxf(s2 / se - mu * mu, 1e-4f));
        e[j]        = mu * bn5g[j]        + bn5b[j];
        e[j + HDIM] = sg * bn5g[HDIM + j] + bn5b[HDIM + j];
    }
    __syncthreads();
    float acc = fc6_b[j];
    for (int k = 0; k < 2 * HDIM; k++) acc += e[k] * fc6_w[(size_t)k * FDIM + j];
    const float em = acc * bn6g[j] + bn6b[j];
    g_emb[b * FDIM + j] = em;

    __shared__ float red[256];
    red[j] = em * em;
    __syncthreads();
    for (int st = 128; st > 0; st >>= 1) { if (j < st) red[j] += red[j + st]; __syncthreads(); }
    const float nrmv = fmaxf(sqrtf(red[0]), 1e-12f);
    __shared__ float emv[256];
    emv[j] = em;
    __syncthreads();
    if (write_cls && j < NCLS) {
        float c = cls_b[j];
        for (int k = 0; k < FDIM; k++) c += (emv[k] / nrmv) * cls_w[(size_t)k * NCLS + j];
        out_cls[b * NCLS + j] = c;
    }
    for (int i = 0; i < 4; i++) {
        const float* W = arn_w2 + (size_t)i * FDIM * FDIM;
        float a2 = 0.f;
        for (int k = 0; k < FDIM; k++) a2 += emv[k] * W[(size_t)k * FDIM + j];
        g_evec[((size_t)i * BDIM + b) * FDIM + j] = a2;
    }
}

__global__ __launch_bounds__(256) void k_ola(float* __restrict__ out)
{
    const int idx = blockIdx.x * blockDim.x + threadIdx.x;
    if (idx >= BDIM * LSIG) return;
    const int b = idx / LSIG;
    const int i = idx - b * LSIG;
    const int t = i / SHIFT;
    const int j = i - t * SHIFT;
    const float* yb = g_y + (size_t)b * TIN * FRAME;
    float v = yb[(size_t)t * FRAME + j];
    if (t > 0) { v += yb[(size_t)(t - 1) * FRAME + j + SHIFT]; v *= 0.5f; }
    out[idx] = v;
}

// ---------------- launch ----------------
extern "C" void kernel_launch(void* const* d_in, const int* in_sizes, int n_in,
                              void* d_out, int out_size)
{
    const float* input   = (const float*)d_in[0];
    const float* anchor  = (const float*)d_in[1];
    const int*   aux_len = (const int*)  d_in[2];
    const float* in_w    = (const float*)d_in[4];
    const float* in_b    = (const float*)d_in[5];
    const float* out_w   = (const float*)d_in[6];
    const float* out_b   = (const float*)d_in[7];
    const float* gln_g   = (const float*)d_in[8];
    const float* gln_b   = (const float*)d_in[9];
    const float* ecapa_w = (const float*)d_in[10];
    const float* ecapa_b = (const float*)d_in[11];
    const float* att_w1  = (const float*)d_in[12];
    const float* att_b1  = (const float*)d_in[13];
    const float* attbn_g = (const float*)d_in[14];
    const float* attbn_b = (const float*)d_in[15];
    const float* att_w2  = (const float*)d_in[16];
    const float* att_b2  = (const float*)d_in[17];
    const float* bn5_g   = (const float*)d_in[18];
    const float* bn5_b   = (const float*)d_in[19];
    const float* fc6_w   = (const float*)d_in[20];
    const float* fc6_b   = (const float*)d_in[21];
    const float* bn6_g   = (const float*)d_in[22];
    const float* bn6_b   = (const float*)d_in[23];
    const float* cls_w   = (const float*)d_in[24];
    const float* cls_b   = (const float*)d_in[25];
    const float* arn_w1  = (const float*)d_in[26];
    const float* arn_w2  = (const float*)d_in[27];
    const float* arn_b   = (const float*)d_in[28];

    float *p_out, *p_out2, *p_aux, *p_h, *p_a, *p_logits, *p_y;
    cudaGetSymbolAddress((void**)&p_out,    g_out);
    cudaGetSymbolAddress((void**)&p_out2,   g_out2);
    cudaGetSymbolAddress((void**)&p_aux,    g_aux);
    cudaGetSymbolAddress((void**)&p_h,      g_h);
    cudaGetSymbolAddress((void**)&p_a,      g_a);
    cudaGetSymbolAddress((void**)&p_logits, g_logits);
    cudaGetSymbolAddress((void**)&p_y,      g_y);

    __nv_bfloat16 *pw_in_h, *pw_in_l, *pw_ec_h, *pw_ec_l, *pw_a1_h, *pw_a1_l,
                  *pw_a2_h, *pw_a2_l, *pw_ar_h, *pw_ar_l, *pw_ou_h, *pw_ou_l;
    cudaGetSymbolAddress((void**)&pw_in_h, w_in_hi);  cudaGetSymbolAddress((void**)&pw_in_l, w_in_lo);
    cudaGetSymbolAddress((void**)&pw_ec_h, w_ec_hi);  cudaGetSymbolAddress((void**)&pw_ec_l, w_ec_lo);
    cudaGetSymbolAddress((void**)&pw_a1_h, w_a1_hi);  cudaGetSymbolAddress((void**)&pw_a1_l, w_a1_lo);
    cudaGetSymbolAddress((void**)&pw_a2_h, w_a2_hi);  cudaGetSymbolAddress((void**)&pw_a2_l, w_a2_lo);
    cudaGetSymbolAddress((void**)&pw_ar_h, w_arn_hi); cudaGetSymbolAddress((void**)&pw_ar_l, w_arn_lo);
    cudaGetSymbolAddress((void**)&pw_ou_h, w_out_hi); cudaGetSymbolAddress((void**)&pw_ou_l, w_out_lo);

    // ---- single fused weight-prep (tiled transpose) ----
    PrepArgs pa;
    int toff = 0;
    auto reg = [&](int r, const float* s, __nv_bfloat16* h, __nv_bfloat16* l, int K, int N) {
        pa.src[r] = s; pa.hi[r] = h; pa.lo[r] = l; pa.K[r] = K; pa.N[r] = N;
        pa.toff[r] = toff; toff += (K / 32) * (N / 32);
    };
    reg(0, in_w,    pw_in_h, pw_in_l, 320, 256);
    reg(1, ecapa_w, pw_ec_h, pw_ec_l, 256, 256);
    reg(2, att_w1,  pw_a1_h, pw_a1_l, 256, 256);
    reg(3, att_w2,  pw_a2_h, pw_a2_l, 256, 256);
    for (int i = 0; i < 4; i++)
        reg(4 + i, arn_w1 + (size_t)i * 65536, pw_ar_h + (size_t)i * 65536,
            pw_ar_l + (size_t)i * 65536, 256, 256);
    reg(8, out_w, pw_ou_h, pw_ou_l, 256, 320);
    pa.toff[9] = toff;
    pa.src[9] = out_w; pa.hi[9] = pw_ou_h; pa.lo[9] = pw_ou_l; pa.K[9] = 256; pa.N[9] = 320;
    pa.toff[10] = toff;
    k_prep_all<<<toff, 256>>>(pa);

    const int SM128 = 2 * (64 * 128) + 2 * (128 * 128);   // 49152
    const int SM160 = 2 * (64 * 128) + 2 * (160 * 128);   // 57344
    cudaFuncSetAttribute(k_tgemm<128,0,4>, cudaFuncAttributeMaxDynamicSharedMemorySize, SM128);
    cudaFuncSetAttribute(k_tgemm<128,1,4>, cudaFuncAttributeMaxDynamicSharedMemorySize, SM128);
    cudaFuncSetAttribute(k_tgemm<128,2,4>, cudaFuncAttributeMaxDynamicSharedMemorySize, SM128);
    cudaFuncSetAttribute(k_tgemm<128,3,4>, cudaFuncAttributeMaxDynamicSharedMemorySize, SM128);
    cudaFuncSetAttribute(k_tgemm<128,4,4>, cudaFuncAttributeMaxDynamicSharedMemorySize, SM128);
    cudaFuncSetAttribute(k_tgemm<160,3,3>, cudaFuncAttributeMaxDynamicSharedMemorySize, SM160);

    // 1. merged encoders: x blocks [0,16) -> input, [16,23) -> anchor; z = 2 N-halves
    k_tgemm<128,0,4><<<dim3(23, 32, 2), 256, SM128>>>(input, pw_in_h, pw_in_l, p_out, in_b,
                                                      nullptr, nullptr, nullptr, TIN, FRAME, FDIM, LSIG, 0,
                                                      anchor, p_aux, TA, LAUX, 16);
    // 2. GLN partials (combine folded into next GEMM)
    k_gln_part<<<dim3(32, 16), 256>>>(aux_len);
    // 3. GLN + ecapa + relu
    k_tgemm<128,1,4><<<dim3(7, 32, 2), 256, SM128>>>(p_aux, pw_ec_h, pw_ec_l, p_h, gln_g, gln_b,
                                                     ecapa_b, aux_len, TA, FDIM, HDIM, 0, 0,
                                                     nullptr, nullptr, 0, 0, 0);
    // 4. h stats + attention bias
    k_hpart<<<dim3(32, NSLC), 256>>>(aux_len);
    k_hcomb<<<32, 256>>>(aux_len, att_w1, att_b1);
    // 5. attention conv1(+relu+bn+tanh)
    k_tgemm<128,2,4><<<dim3(7, 32, 2), 256, SM128>>>(p_h, pw_a1_h, pw_a1_l, p_a, attbn_g, attbn_b,
                                                     nullptr, nullptr, TA, HDIM, HDIM, 0, 0,
                                                     nullptr, nullptr, 0, 0, 0);
    // 6. attention conv2
    k_tgemm<128,3,4><<<dim3(7, 32, 2), 256, SM128>>>(p_a, pw_a2_h, pw_a2_l, p_logits, att_b2,
                                                     nullptr, nullptr, nullptr, TA, HDIM, HDIM, 0, 0,
                                                     nullptr, nullptr, 0, 0, 0);
    // 7. pool + emb + classifier + evec
    k_ppart<<<dim3(32, NSLC), 256>>>(aux_len);
    const int write_cls = (out_size >= BDIM * LSIG + BDIM * NCLS) ? 1 : 0;
    k_pcomb<<<32, 256>>>(bn5_g, bn5_b, fc6_w, fc6_b, bn6_g, bn6_b, cls_w, cls_b,
                         arn_w2, (float*)d_out + (size_t)BDIM * LSIG, write_cls);
    // 8-11. 4 ARN residual blocks (ping-pong)
    const float* src = p_out;
    float*       dst = p_out2;
    for (int i = 0; i < 4; i++) {
        k_tgemm<128,4,4><<<dim3(16, 32, 2), 256, SM128>>>(src, pw_ar_h + (size_t)i * 65536,
                                                          pw_ar_l + (size_t)i * 65536, dst,
                                                          arn_b + i * FDIM, nullptr, nullptr,
                                                          nullptr, TIN, FDIM, FDIM, 0, i,
                                                          nullptr, nullptr, 0, 0, 0);
        const float* tmp = dst; dst = (float*)src; src = tmp;
    }
    // 12. decoder (N=320 in two 160-col halves)
    k_tgemm<160,3,3><<<dim3(16, 32, 2), 256, SM160>>>(src, pw_ou_h, pw_ou_l, p_y, out_b,
                                                      nullptr, nullptr, nullptr, TIN, FDIM, FRAME, 0, 0,
                                                      nullptr, nullptr, 0, 0, 0);
    // 13. OLA
    k_ola<<<(BDIM * LSIG + 255) / 256, 256>>>((float*)d_out);
}